// round 12
// baseline (speedup 1.0000x reference)
#include <cuda_runtime.h>
#include <cuda_bf16.h>

// Problem constants (B=8, T=4096, C=512)
#define B_DIM 8
#define T_DIM 4096
#define C_DIM 512
#define SEGLEN   32              // timesteps per thread-segment
#define SEGS_PB  16              // segments per block
#define CHUNKLEN (SEGLEN * SEGS_PB)     // 512 timesteps per chunk/block
#define NCHUNK   (T_DIM / CHUNKLEN)     // 8 chunks per (b, channel) chain
#define NSEGTOT  (T_DIM / SEGLEN)       // 128 segments per chain
#define CPB   32                 // channels per block
#define PAIRS 16                 // channel-pairs per block
#define UNR   8
#define XS2   (C_DIM / 2)        // float2 stride per timestep in x
#define OS4   (C_DIM * 2 / 4)    // float4 stride per timestep in out

// scratch: segment finals, chunk aggregates, chunk starts
__device__ float g_SF[B_DIM * NSEGTOT * C_DIM * 2];   // 4 MB
__device__ float g_CF[B_DIM * NCHUNK * C_DIM * 2];    // 256 KB
__device__ float g_CS[B_DIM * NCHUNK * C_DIM * 2];    // 256 KB

__device__ __forceinline__ void step2(float2& hr, float2& hi,
                                      const float2 Ar, const float2 Ai,
                                      const float2 xv) {
    float2 nr, ni;
    nr.x = fmaf(hr.x, Ar.x, fmaf(-hi.x, Ai.x, xv.x));
    ni.x = fmaf(hr.x, Ai.x, hi.x * Ar.x);
    nr.y = fmaf(hr.y, Ar.y, fmaf(-hi.y, Ai.y, xv.y));
    ni.y = fmaf(hr.y, Ai.y, hi.y * Ar.y);
    hr = nr; hi = ni;
}

__device__ __forceinline__ void cfma(float& er, float& ei, float pr, float pi,
                                     float lr, float li) {
    float nr = fmaf(pr, er, fmaf(-pi, ei, lr));
    float ni = fmaf(pr, ei, fmaf(pi, er, li));
    er = nr; ei = ni;
}

// A^32 via 5 complex squarings
__device__ __forceinline__ void pow32(float& pr, float& pi) {
    #pragma unroll
    for (int s = 0; s < 5; s++) {
        float nr = pr * pr - pi * pi;
        float ni = 2.f * pr * pi;
        pr = nr; pi = ni;
    }
}

// ---------------- K1: zero-start segment scans + chunk aggregates ----------------
__global__ __launch_bounds__(256)
void k1_scan(const float* __restrict__ x,
             const float* __restrict__ Ar_g,
             const float* __restrict__ Ai_g) {
    __shared__ float s_fr[SEGS_PB][CPB];
    __shared__ float s_fi[SEGS_PB][CPB];

    const int pair  = threadIdx.x & (PAIRS - 1);
    const int seg   = threadIdx.x >> 4;
    const int b     = blockIdx.x >> 7;          // 16 slabs * 8 chunks = 128 per b
    const int rem   = blockIdx.x & 127;
    const int slab  = rem >> 3;
    const int chunk = rem & 7;
    const int c0    = slab * CPB + pair * 2;
    const int sg    = chunk * SEGS_PB + seg;    // global segment index 0..127
    const int t0    = sg * SEGLEN;

    const float2 Ar = *reinterpret_cast<const float2*>(Ar_g + c0);
    const float2 Ai = *reinterpret_cast<const float2*>(Ai_g + c0);

    const float2* xq = reinterpret_cast<const float2*>(x + (size_t)b * T_DIM * C_DIM)
                       + (size_t)t0 * XS2 + (c0 >> 1);

    float2 hr = make_float2(0.f, 0.f);
    float2 hi = make_float2(0.f, 0.f);
    #pragma unroll 1
    for (int j = 0; j < SEGLEN; j += UNR) {
        float2 xv[UNR];
        #pragma unroll
        for (int k = 0; k < UNR; k++)
            xv[k] = xq[(size_t)(j + k) * XS2];
        #pragma unroll
        for (int k = 0; k < UNR; k++)
            step2(hr, hi, Ar, Ai, xv[k]);
    }

    // segment finals -> global scratch (coalesced float4) and smem
    *reinterpret_cast<float4*>(g_SF + ((size_t)(b * NSEGTOT + sg) * C_DIM + c0) * 2)
        = make_float4(hr.x, hi.x, hr.y, hi.y);
    s_fr[seg][pair * 2 + 0] = hr.x;  s_fi[seg][pair * 2 + 0] = hi.x;
    s_fr[seg][pair * 2 + 1] = hr.y;  s_fi[seg][pair * 2 + 1] = hi.y;
    __syncthreads();

    // chunk aggregate: serial over 16 segment finals (zero-start): acc = A^32*acc + F[s]
    if (threadIdx.x < CPB) {
        const int ch = threadIdx.x;
        const int c  = slab * CPB + ch;
        float pr = Ar_g[c], pi = Ai_g[c];
        pow32(pr, pi);
        float ar = 0.f, ai = 0.f;
        #pragma unroll 4
        for (int s = 0; s < SEGS_PB; s++)
            cfma(ar, ai, pr, pi, s_fr[s][ch], s_fi[s][ch]);
        float2* cf = reinterpret_cast<float2*>(
            g_CF + ((size_t)(b * NCHUNK + chunk) * C_DIM + c) * 2);
        *cf = make_float2(ar, ai);
    }
}

// ---------------- K2: per-channel prefix over 8 chunk aggregates ----------------
__global__ __launch_bounds__(256)
void k2_combine(const float* __restrict__ Ar_g,
                const float* __restrict__ Ai_g,
                const float* __restrict__ h0r_g,
                const float* __restrict__ h0i_g) {
    const int idx = blockIdx.x * blockDim.x + threadIdx.x;   // 4096 threads
    const int b = idx >> 9;
    const int c = idx & 511;

    float pr = Ar_g[c], pi = Ai_g[c];
    pow32(pr, pi);                       // A^32
    #pragma unroll
    for (int s = 0; s < 4; s++) {        // -> A^512
        float nr = pr * pr - pi * pi;
        float ni = 2.f * pr * pi;
        pr = nr; pi = ni;
    }

    float cr = h0r_g[(size_t)b * C_DIM + c];
    float ci = h0i_g[(size_t)b * C_DIM + c];
    #pragma unroll
    for (int k = 0; k < NCHUNK; k++) {
        const size_t o = ((size_t)(b * NCHUNK + k) * C_DIM + c) * 2;
        g_CS[o + 0] = cr;
        g_CS[o + 1] = ci;
        cfma(cr, ci, pr, pi, g_CF[o + 0], g_CF[o + 1]);
    }
}

// ---------------- K3: derive segment starts, replay, write output ----------------
__global__ __launch_bounds__(256)
void k3_replay(const float* __restrict__ x,
               const float* __restrict__ Ar_g,
               const float* __restrict__ Ai_g,
               float* __restrict__ out) {
    __shared__ float s_sr[SEGS_PB][CPB];
    __shared__ float s_si[SEGS_PB][CPB];

    const int pair  = threadIdx.x & (PAIRS - 1);
    const int seg   = threadIdx.x >> 4;
    const int b     = blockIdx.x >> 7;
    const int rem   = blockIdx.x & 127;
    const int slab  = rem >> 3;
    const int chunk = rem & 7;
    const int c0    = slab * CPB + pair * 2;
    const int sg    = chunk * SEGS_PB + seg;
    const int t0    = sg * SEGLEN;

    // 32 threads: chunk start -> 16 segment starts (serial, exact by linearity)
    if (threadIdx.x < CPB) {
        const int ch = threadIdx.x;
        const int c  = slab * CPB + ch;
        float pr = Ar_g[c], pi = Ai_g[c];
        pow32(pr, pi);                   // A^32
        const size_t so = ((size_t)(b * NCHUNK + chunk) * C_DIM + c) * 2;
        float cr = g_CS[so + 0];
        float ci = g_CS[so + 1];
        #pragma unroll 4
        for (int s = 0; s < SEGS_PB; s++) {
            s_sr[s][ch] = cr;
            s_si[s][ch] = ci;
            const size_t fo = ((size_t)(b * NSEGTOT + chunk * SEGS_PB + s) * C_DIM + c) * 2;
            cfma(cr, ci, pr, pi, g_SF[fo + 0], g_SF[fo + 1]);
        }
    }
    __syncthreads();

    const float2 Ar = *reinterpret_cast<const float2*>(Ar_g + c0);
    const float2 Ai = *reinterpret_cast<const float2*>(Ai_g + c0);

    float2 hr = make_float2(s_sr[seg][pair * 2 + 0], s_sr[seg][pair * 2 + 1]);
    float2 hi = make_float2(s_si[seg][pair * 2 + 0], s_si[seg][pair * 2 + 1]);

    const float2* xq = reinterpret_cast<const float2*>(x + (size_t)b * T_DIM * C_DIM)
                       + (size_t)t0 * XS2 + (c0 >> 1);
    float4* op = reinterpret_cast<float4*>(out + (size_t)b * T_DIM * C_DIM * 2)
                 + (size_t)t0 * OS4 + (c0 >> 1);

    #pragma unroll 1
    for (int j = 0; j < SEGLEN; j += UNR) {
        float2 xv[UNR];
        #pragma unroll
        for (int k = 0; k < UNR; k++)
            xv[k] = __ldcs(xq + (size_t)(j + k) * XS2);   // read-once: evict-first
        #pragma unroll
        for (int k = 0; k < UNR; k++) {
            step2(hr, hi, Ar, Ai, xv[k]);
            __stcs(op + (size_t)(j + k) * OS4,
                   make_float4(hr.x, hi.x, hr.y, hi.y));  // streaming store
        }
    }
}

extern "C" void kernel_launch(void* const* d_in, const int* in_sizes, int n_in,
                              void* d_out, int out_size) {
    const float* x   = (const float*)d_in[0];   // (B, T, C)
    const float* Ar  = (const float*)d_in[1];   // (C,)
    const float* Ai  = (const float*)d_in[2];   // (C,)
    const float* h0r = (const float*)d_in[3];   // (B, C)
    const float* h0i = (const float*)d_in[4];   // (B, C)
    float* out = (float*)d_out;                 // (B, T, C, 2)

    dim3 gridA(B_DIM * 16 * NCHUNK);            // 1024 blocks
    k1_scan<<<gridA, 256>>>(x, Ar, Ai);
    k2_combine<<<16, 256>>>(Ar, Ai, h0r, h0i);  // 4096 threads
    k3_replay<<<gridA, 256>>>(x, Ar, Ai, out);
}

// round 13
// speedup vs baseline: 1.2894x; 1.2894x over previous
#include <cuda_runtime.h>
#include <cuda_bf16.h>

// Problem constants (B=8, T=4096, C=512)
#define B_DIM 8
#define T_DIM 4096
#define C_DIM 512
#define CPB   16                 // channels per block
#define PAIRS 8                  // channel-pairs per block (2 ch per thread)
#define NSEG  64                 // time segments per block
#define SEG   64                 // timesteps per segment (NSEG*SEG = T)
#define UNR   8                  // load batch depth
#define XS2   (C_DIM / 2)        // float2 stride per timestep in x
#define OS4   (C_DIM * 2 / 4)    // float4 stride per timestep in out

// 2 independent complex recurrence steps (ch0 = .x, ch1 = .y)
__device__ __forceinline__ void step2(float2& hr, float2& hi,
                                      const float2 Ar, const float2 Ai,
                                      const float2 xv) {
    float2 nr, ni;
    nr.x = fmaf(hr.x, Ar.x, fmaf(-hi.x, Ai.x, xv.x));
    ni.x = fmaf(hr.x, Ai.x, hi.x * Ar.x);
    nr.y = fmaf(hr.y, Ar.y, fmaf(-hi.y, Ai.y, xv.y));
    ni.y = fmaf(hr.y, Ai.y, hi.y * Ar.y);
    hr = nr; hi = ni;
}

__global__ __launch_bounds__(PAIRS * NSEG, 1)
void stateful_recurrent_kernel(const float* __restrict__ x,
                               const float* __restrict__ Ar_g,
                               const float* __restrict__ Ai_g,
                               const float* __restrict__ h0r_g,
                               const float* __restrict__ h0i_g,
                               float* __restrict__ out) {
    // Phase A finals, then (in place) segment-start states
    __shared__ float s_r[NSEG][CPB];
    __shared__ float s_i[NSEG][CPB];

    const int pair = threadIdx.x & (PAIRS - 1);   // 0..7
    const int seg  = threadIdx.x >> 3;            // 0..63
    const int b    = blockIdx.x >> 5;             // 32 slabs per b
    const int slab = blockIdx.x & 31;
    const int c0   = slab * CPB + pair * 2;       // first of this thread's 2 channels

    const float2 Ar = *reinterpret_cast<const float2*>(Ar_g + c0);
    const float2 Ai = *reinterpret_cast<const float2*>(Ai_g + c0);

    const float2* xp = reinterpret_cast<const float2*>(x + (size_t)b * T_DIM * C_DIM)
                       + (c0 >> 1);
    const int t0 = seg * SEG;

    // ---------------- Phase A: zero-start local scan of this segment --------------
    float2 hr = make_float2(0.f, 0.f);
    float2 hi = make_float2(0.f, 0.f);
    {
        const float2* xq = xp + (size_t)t0 * XS2;
        #pragma unroll 1
        for (int j = 0; j < SEG; j += UNR) {
            float2 xv[UNR];
            #pragma unroll
            for (int k = 0; k < UNR; k++)
                xv[k] = xq[(size_t)(j + k) * XS2];
            #pragma unroll
            for (int k = 0; k < UNR; k++)
                step2(hr, hi, Ar, Ai, xv[k]);
        }
    }
    s_r[seg][pair * 2 + 0] = hr.x;  s_i[seg][pair * 2 + 0] = hi.x;
    s_r[seg][pair * 2 + 1] = hr.y;  s_i[seg][pair * 2 + 1] = hi.y;
    __syncthreads();

    // -------- Phase B: serial prefix over 64 segments (16 threads, 1 channel each) --------
    if (threadIdx.x < CPB) {
        const int ch = threadIdx.x;
        const int c  = slab * CPB + ch;
        float ar = Ar_g[c], ai = Ai_g[c];
        // A^SEG = A^64 via 6 complex squarings
        float pr = ar, pi = ai;
        #pragma unroll
        for (int s = 0; s < 6; s++) {
            float nr = pr * pr - pi * pi;
            float ni = 2.f * pr * pi;
            pr = nr; pi = ni;
        }
        float cr = h0r_g[(size_t)b * C_DIM + c];
        float ci = h0i_g[(size_t)b * C_DIM + c];
        float fr = s_r[0][ch], fi = s_i[0][ch];
        #pragma unroll 4
        for (int s = 0; s < NSEG; s++) {
            float frn = 0.f, fin = 0.f;
            if (s + 1 < NSEG) { frn = s_r[s + 1][ch]; fin = s_i[s + 1][ch]; }
            s_r[s][ch] = cr;  s_i[s][ch] = ci;   // overwrite final with start, in place
            float nr = fmaf(pr, cr, fmaf(-pi, ci, fr));
            float ni = fmaf(pr, ci, fmaf(pi, cr, fi));
            cr = nr; ci = ni;
            fr = frn; fi = fin;
        }
    }
    __syncthreads();

    // ---------------- Phase C: replay from correct start, write out ----------------
    hr.x = s_r[seg][pair * 2 + 0];  hi.x = s_i[seg][pair * 2 + 0];
    hr.y = s_r[seg][pair * 2 + 1];  hi.y = s_i[seg][pair * 2 + 1];
    {
        const float2* xq = xp + (size_t)t0 * XS2;
        float4* op = reinterpret_cast<float4*>(out + ((size_t)b * T_DIM * C_DIM) * 2)
                     + (size_t)t0 * OS4 + (c0 >> 1);
        #pragma unroll 1
        for (int j = 0; j < SEG; j += UNR) {
            float2 xv[UNR];
            #pragma unroll
            for (int k = 0; k < UNR; k++)
                xv[k] = xq[(size_t)(j + k) * XS2];      // L2-resident reread
            #pragma unroll
            for (int k = 0; k < UNR; k++) {
                step2(hr, hi, Ar, Ai, xv[k]);
                __stcs(op + (size_t)(j + k) * OS4,
                       make_float4(hr.x, hi.x, hr.y, hi.y));  // streaming store
            }
        }
    }
}

extern "C" void kernel_launch(void* const* d_in, const int* in_sizes, int n_in,
                              void* d_out, int out_size) {
    const float* x   = (const float*)d_in[0];   // (B, T, C)
    const float* Ar  = (const float*)d_in[1];   // (C,)
    const float* Ai  = (const float*)d_in[2];   // (C,)
    const float* h0r = (const float*)d_in[3];   // (B, C)
    const float* h0i = (const float*)d_in[4];   // (B, C)
    float* out = (float*)d_out;                 // (B, T, C, 2)

    dim3 grid(B_DIM * (C_DIM / CPB));           // 8 * 32 = 256 blocks
    dim3 block(PAIRS * NSEG);                   // 512 threads
    stateful_recurrent_kernel<<<grid, block>>>(x, Ar, Ai, h0r, h0i, out);
}